// round 1
// baseline (speedup 1.0000x reference)
#include <cuda_runtime.h>

#define Nn 384
#define Dm 256
#define MARGIN 0.2f
#define ANCH 4
#define NBLK (Nn / ANCH)   // 96
#define NTHR 384
#define NWARP 12

__device__ float g_scale[Nn];
__device__ float g_sq[Nn];
__device__ float g_psum[NBLK];
__device__ int   g_pcnt[NBLK];

// ---------------------------------------------------------------------------
// Kernel 1: per-row inverse norm + squared-norm of normalized row
// ---------------------------------------------------------------------------
__global__ void k_norm(const float* __restrict__ e) {
    int row = blockIdx.x, t = threadIdx.x;   // 256 threads
    float v = e[row * Dm + t];
    float s = v * v;
    #pragma unroll
    for (int o = 16; o > 0; o >>= 1) s += __shfl_xor_sync(0xffffffffu, s, o);
    __shared__ float red[8];
    if ((t & 31) == 0) red[t >> 5] = s;
    __syncthreads();
    if (t == 0) {
        float tot = 0.0f;
        #pragma unroll
        for (int i = 0; i < 8; i++) tot += red[i];
        float nrm = sqrtf(tot);
        float sc  = 1.0f / fmaxf(nrm, 1e-12f);
        float q   = nrm * sc;                 // ~1.0, matches ref's sq of normalized e
        g_scale[row] = sc;
        g_sq[row]    = q * q;
    }
}

// ---------------------------------------------------------------------------
// Kernel 2: fused distance row + semi-hard triplet scan, 4 anchors per block
// ---------------------------------------------------------------------------
__global__ void __launch_bounds__(NTHR) k_triplet(const float* __restrict__ e,
                                                  const int*   __restrict__ lab) {
    __shared__ float ea[ANCH * Dm];      // scaled anchor rows
    __shared__ float Drow[ANCH][Nn];     // distances anchor -> all j
    __shared__ int   slab[Nn];
    __shared__ float pd[Nn];             // compacted positive distances
    __shared__ int   wcnt[NWARP];
    __shared__ float rsum[NWARP];
    __shared__ int   rcnt[NWARP];

    const int t = threadIdx.x, w = t >> 5, lane = t & 31;
    const int a0 = blockIdx.x * ANCH;

    if (t < Nn) slab[t] = lab[t];
    for (int i = t; i < ANCH * Dm; i += NTHR) {
        int aa = i >> 8;                 // / Dm
        ea[i] = e[(a0 + aa) * Dm + (i & (Dm - 1))] * g_scale[a0 + aa];
    }
    __syncthreads();

    // Anchor fragments into registers: lane owns k = kk*32 + lane
    float ear[ANCH][8];
    #pragma unroll
    for (int kk = 0; kk < 8; kk++)
        #pragma unroll
        for (int aa = 0; aa < ANCH; aa++)
            ear[aa][kk] = ea[aa * Dm + kk * 32 + lane];

    // Phase 2: warp-cooperative dots, 4 anchors amortized per loaded value
    for (int j = w; j < Nn; j += NWARP) {
        const float* __restrict__ ej = e + j * Dm;
        float p0 = 0.f, p1 = 0.f, p2 = 0.f, p3 = 0.f;
        #pragma unroll
        for (int kk = 0; kk < 8; kk++) {
            float v = ej[kk * 32 + lane];
            p0 = fmaf(ear[0][kk], v, p0);
            p1 = fmaf(ear[1][kk], v, p1);
            p2 = fmaf(ear[2][kk], v, p2);
            p3 = fmaf(ear[3][kk], v, p3);
        }
        #pragma unroll
        for (int o = 16; o > 0; o >>= 1) {
            p0 += __shfl_xor_sync(0xffffffffu, p0, o);
            p1 += __shfl_xor_sync(0xffffffffu, p1, o);
            p2 += __shfl_xor_sync(0xffffffffu, p2, o);
            p3 += __shfl_xor_sync(0xffffffffu, p3, o);
        }
        if (lane == 0) {
            float sj = g_scale[j], qj = g_sq[j];
            float ds[ANCH] = {p0, p1, p2, p3};
            #pragma unroll
            for (int aa = 0; aa < ANCH; aa++) {
                float d2 = g_sq[a0 + aa] + qj - 2.0f * sj * ds[aa];
                d2 = fmaxf(d2, 0.0f);
                Drow[aa][j] = (d2 > 0.0f) ? sqrtf(d2) : 0.0f;
            }
        }
    }
    __syncthreads();

    // Phase 3+4: per anchor, deterministic ballot-compaction of positives,
    // then every thread (= one negative) scans the positive list.
    float lsum = 0.0f;
    int   lcnt = 0;
    for (int aa = 0; aa < ANCH; aa++) {
        const int a  = a0 + aa;
        const int la = slab[a];
        bool isp = (slab[t] == la) && (t != a);
        unsigned m = __ballot_sync(0xffffffffu, isp);
        if (lane == 0) wcnt[w] = __popc(m);
        __syncthreads();
        int off = 0;
        #pragma unroll
        for (int i = 0; i < NWARP; i++) {
            if (i < w) off += wcnt[i];
        }
        int npos = 0;
        #pragma unroll
        for (int i = 0; i < NWARP; i++) npos += wcnt[i];
        if (isp) pd[off + __popc(m & ((1u << lane) - 1u))] = Drow[aa][t];
        __syncthreads();

        if (slab[t] != la) {
            float dn = Drow[aa][t];
            for (int i = 0; i < npos; i++) {
                float tm = dn - pd[i];
                // semihard & loss>0  <=>  0 < tm < MARGIN (tm==MARGIN adds 0)
                if (tm > 0.0f && tm < MARGIN) { lsum += (MARGIN - tm); lcnt++; }
            }
        }
        __syncthreads();
    }

    // Block reduction (fixed order -> deterministic)
    #pragma unroll
    for (int o = 16; o > 0; o >>= 1) {
        lsum += __shfl_xor_sync(0xffffffffu, lsum, o);
        lcnt += __shfl_xor_sync(0xffffffffu, lcnt, o);
    }
    if (lane == 0) { rsum[w] = lsum; rcnt[w] = lcnt; }
    __syncthreads();
    if (t == 0) {
        float s = 0.0f; int c = 0;
        #pragma unroll
        for (int i = 0; i < NWARP; i++) { s += rsum[i]; c += rcnt[i]; }
        g_psum[blockIdx.x] = s;
        g_pcnt[blockIdx.x] = c;
    }
}

// ---------------------------------------------------------------------------
// Kernel 3: final deterministic reduction of 96 block partials
// ---------------------------------------------------------------------------
__global__ void k_final(float* __restrict__ out) {
    int t = threadIdx.x;                 // 128 threads
    float s = (t < NBLK) ? g_psum[t] : 0.0f;
    int   c = (t < NBLK) ? g_pcnt[t] : 0;
    #pragma unroll
    for (int o = 16; o > 0; o >>= 1) {
        s += __shfl_xor_sync(0xffffffffu, s, o);
        c += __shfl_xor_sync(0xffffffffu, c, o);
    }
    __shared__ float rs[4];
    __shared__ int   rc[4];
    int w = t >> 5, lane = t & 31;
    if (lane == 0) { rs[w] = s; rc[w] = c; }
    __syncthreads();
    if (t == 0) {
        float ts = rs[0] + rs[1] + rs[2] + rs[3];
        int   tc = rc[0] + rc[1] + rc[2] + rc[3];
        out[0] = (tc > 0) ? (ts / (float)tc) : 0.0f;
    }
}

extern "C" void kernel_launch(void* const* d_in, const int* in_sizes, int n_in,
                              void* d_out, int out_size) {
    const float* e   = (const float*)d_in[0];
    const int*   lab = (const int*)d_in[1];
    k_norm<<<Nn, Dm>>>(e);
    k_triplet<<<NBLK, NTHR>>>(e, lab);
    k_final<<<1, 128>>>((float*)d_out);
}

// round 2
// speedup vs baseline: 2.1182x; 2.1182x over previous
#include <cuda_runtime.h>

#define Nn 384
#define Dm 256
#define MARGIN 0.2f
#define ANCH 4
#define NBLK (Nn / ANCH)   // 96
#define NTHR 384
#define NWARP 12
#define JB 4

__device__ float    g_psum[NBLK];
__device__ int      g_pcnt[NBLK];
__device__ unsigned g_flag;      // zero-init; last block resets to 0 each run

__global__ void __launch_bounds__(NTHR, 1)
k_fused(const float* __restrict__ e, const int* __restrict__ lab,
        float* __restrict__ out) {
    __shared__ float ea[ANCH * Dm];      // raw anchor rows
    __shared__ float sa[ANCH];           // anchor inverse norms
    __shared__ float Drow[ANCH][Nn];     // raw dots -> distances (in place)
    __shared__ float sssq[Nn];           // raw squared norms per j
    __shared__ int   slab[Nn];
    __shared__ float pd[Nn];             // compacted positive distances
    __shared__ int   wcnt[NWARP];
    __shared__ float rsum[NWARP];
    __shared__ int   rcnt[NWARP];
    __shared__ int   s_last;

    const int t = threadIdx.x, w = t >> 5, lane = t & 31;
    const int a0 = blockIdx.x * ANCH;

    if (t < Nn) slab[t] = lab[t];
    for (int i = t; i < ANCH * Dm; i += NTHR) ea[i] = e[a0 * Dm + i];
    __syncthreads();

    // Anchor inverse norms (warps 0..3, one anchor each)
    if (w < ANCH) {
        float s = 0.0f;
        #pragma unroll
        for (int kk = 0; kk < 8; kk++) {
            float v = ea[w * Dm + kk * 32 + lane];
            s = fmaf(v, v, s);
        }
        #pragma unroll
        for (int o = 16; o > 0; o >>= 1) s += __shfl_xor_sync(0xffffffffu, s, o);
        if (lane == 0) sa[w] = rsqrtf(fmaxf(s, 1e-24f));
    }

    // Raw anchor fragments in registers: lane owns k = lane*4..+3 and 128+lane*4..+3
    float4 ar[ANCH][2];
    #pragma unroll
    for (int aa = 0; aa < ANCH; aa++) {
        ar[aa][0] = ((const float4*)(ea + aa * Dm))[lane];
        ar[aa][1] = ((const float4*)(ea + aa * Dm + 128))[lane];
    }
    __syncthreads();

    // ---- Phase 2: raw dots + squared norms, 4 j's per warp iteration ----
    for (int jb = w * JB; jb < Nn; jb += NWARP * JB) {
        float acc[JB][ANCH];
        float ssq[JB];
        #pragma unroll
        for (int jj = 0; jj < JB; jj++) {
            const float4* row = (const float4*)(e + (jb + jj) * Dm);
            float4 v0 = row[lane];
            float4 v1 = row[lane + 32];
            float q = v0.x * v0.x;
            q = fmaf(v0.y, v0.y, q); q = fmaf(v0.z, v0.z, q); q = fmaf(v0.w, v0.w, q);
            q = fmaf(v1.x, v1.x, q); q = fmaf(v1.y, v1.y, q);
            q = fmaf(v1.z, v1.z, q); q = fmaf(v1.w, v1.w, q);
            ssq[jj] = q;
            #pragma unroll
            for (int aa = 0; aa < ANCH; aa++) {
                float s = ar[aa][0].x * v0.x;
                s = fmaf(ar[aa][0].y, v0.y, s);
                s = fmaf(ar[aa][0].z, v0.z, s);
                s = fmaf(ar[aa][0].w, v0.w, s);
                s = fmaf(ar[aa][1].x, v1.x, s);
                s = fmaf(ar[aa][1].y, v1.y, s);
                s = fmaf(ar[aa][1].z, v1.z, s);
                s = fmaf(ar[aa][1].w, v1.w, s);
                acc[jj][aa] = s;
            }
        }
        // 20 overlapping butterfly chains
        #pragma unroll
        for (int o = 16; o > 0; o >>= 1) {
            #pragma unroll
            for (int jj = 0; jj < JB; jj++) {
                ssq[jj] += __shfl_xor_sync(0xffffffffu, ssq[jj], o);
                #pragma unroll
                for (int aa = 0; aa < ANCH; aa++)
                    acc[jj][aa] += __shfl_xor_sync(0xffffffffu, acc[jj][aa], o);
            }
        }
        if (lane == 0) {
            #pragma unroll
            for (int jj = 0; jj < JB; jj++) {
                sssq[jb + jj] = ssq[jj];
                #pragma unroll
                for (int aa = 0; aa < ANCH; aa++)
                    Drow[aa][jb + jj] = acc[jj][aa];
            }
        }
    }
    __syncthreads();

    // ---- Parallel epilogue: raw dot -> distance, thread t handles column j=t ----
    {
        float sj = rsqrtf(fmaxf(sssq[t], 1e-24f));
        #pragma unroll
        for (int aa = 0; aa < ANCH; aa++) {
            float d2 = 2.0f - 2.0f * Drow[aa][t] * sa[aa] * sj;
            d2 = fmaxf(d2, 0.0f);
            Drow[aa][t] = (d2 > 0.0f) ? sqrtf(d2) : 0.0f;
        }
    }
    __syncthreads();

    // ---- Phase 3+4: per anchor, ballot-compaction of positives + negative scan ----
    float lsum = 0.0f;
    int   lcnt = 0;
    for (int aa = 0; aa < ANCH; aa++) {
        const int a  = a0 + aa;
        const int la = slab[a];
        bool isp = (slab[t] == la) && (t != a);
        unsigned m = __ballot_sync(0xffffffffu, isp);
        if (lane == 0) wcnt[w] = __popc(m);
        __syncthreads();
        int off = 0, npos = 0;
        #pragma unroll
        for (int i = 0; i < NWARP; i++) {
            if (i < w) off += wcnt[i];
            npos += wcnt[i];
        }
        if (isp) pd[off + __popc(m & ((1u << lane) - 1u))] = Drow[aa][t];
        __syncthreads();

        if (slab[t] != la) {
            float dn = Drow[aa][t];
            for (int i = 0; i < npos; i++) {
                float tm = dn - pd[i];
                // semihard & loss>0  <=>  0 < tm < MARGIN (tm==MARGIN adds 0)
                if (tm > 0.0f && tm < MARGIN) { lsum += (MARGIN - tm); lcnt++; }
            }
        }
        __syncthreads();
    }

    // ---- Block reduction (fixed order, deterministic) ----
    #pragma unroll
    for (int o = 16; o > 0; o >>= 1) {
        lsum += __shfl_xor_sync(0xffffffffu, lsum, o);
        lcnt += __shfl_xor_sync(0xffffffffu, lcnt, o);
    }
    if (lane == 0) { rsum[w] = lsum; rcnt[w] = lcnt; }
    __syncthreads();
    if (t == 0) {
        float s = 0.0f; int c = 0;
        #pragma unroll
        for (int i = 0; i < NWARP; i++) { s += rsum[i]; c += rcnt[i]; }
        g_psum[blockIdx.x] = s;
        g_pcnt[blockIdx.x] = c;
        __threadfence();
        unsigned old = atomicAdd(&g_flag, 1u);
        s_last = (old == NBLK - 1) ? 1 : 0;
    }
    __syncthreads();

    // ---- Last block folds the 96 partials (deterministic order) ----
    if (s_last) {
        float s2 = (t < NBLK) ? g_psum[t] : 0.0f;
        int   c2 = (t < NBLK) ? g_pcnt[t] : 0;
        #pragma unroll
        for (int o = 16; o > 0; o >>= 1) {
            s2 += __shfl_xor_sync(0xffffffffu, s2, o);
            c2 += __shfl_xor_sync(0xffffffffu, c2, o);
        }
        if (lane == 0 && w < 3) { rsum[w] = s2; rcnt[w] = c2; }
        __syncthreads();
        if (t == 0) {
            float ts = rsum[0] + rsum[1] + rsum[2];
            int   tc = rcnt[0] + rcnt[1] + rcnt[2];
            out[0] = (tc > 0) ? (ts / (float)tc) : 0.0f;
            g_flag = 0;   // reset for next graph replay
        }
    }
}

extern "C" void kernel_launch(void* const* d_in, const int* in_sizes, int n_in,
                              void* d_out, int out_size) {
    const float* e   = (const float*)d_in[0];
    const int*   lab = (const int*)d_in[1];
    k_fused<<<NBLK, NTHR>>>(e, lab, (float*)d_out);
}

// round 3
// speedup vs baseline: 2.5844x; 1.2201x over previous
#include <cuda_runtime.h>

#define Nn 384
#define Dm 256
#define MARGIN 0.2f
#define ANCH 4
#define NBLK (Nn / ANCH)   // 96
#define NTHR 384
#define NWARP 12
#define JB 4

__device__ float    g_psum[NBLK];
__device__ int      g_pcnt[NBLK];
__device__ unsigned g_flag;      // zero-init; last block resets to 0 each run

__global__ void __launch_bounds__(NTHR, 1)
k_fused(const float* __restrict__ e, const int* __restrict__ lab,
        float* __restrict__ out) {
    __shared__ float4 ea4[ANCH * 64];    // raw anchor rows (float4 view)
    __shared__ float  Drow[ANCH][Nn];    // raw dots -> distances (in place)
    __shared__ float  sssq[Nn];          // raw squared norms per j
    __shared__ int    slab[Nn];
    __shared__ float  pd[Nn];            // compacted positive distances
    __shared__ int    wcnt[NWARP];
    __shared__ float  rsum[NWARP];
    __shared__ int    rcnt[NWARP];
    __shared__ int    s_last;

    const int t = threadIdx.x, w = t >> 5, lane = t & 31;
    const int a0 = blockIdx.x * ANCH;

    if (t < Nn) slab[t] = lab[t];
    {
        const float4* src = (const float4*)(e + a0 * Dm);
        for (int i = t; i < ANCH * 64; i += NTHR) ea4[i] = src[i];
    }
    __syncthreads();

    // ---- Phase 2: 8 lanes per j, 4 j's per warp iteration ----
    const int jj = lane >> 3;            // which j within the group of 4
    const int kk = lane & 7;             // which k-slice (8 float4 per lane)

    for (int jb = w * JB; jb < Nn; jb += NWARP * JB) {
        const int j = jb + jj;
        const float4* __restrict__ row = (const float4*)(e + j * Dm);
        float c0 = 0.f, c1 = 0.f, c2 = 0.f, c3 = 0.f, q = 0.f;
        #pragma unroll
        for (int c = 0; c < 8; c++) {
            const int f = kk + 8 * c;
            float4 v  = row[f];
            float4 b0 = ea4[0 * 64 + f];
            float4 b1 = ea4[1 * 64 + f];
            float4 b2 = ea4[2 * 64 + f];
            float4 b3 = ea4[3 * 64 + f];
            q  = fmaf(v.x, v.x, q);  q  = fmaf(v.y, v.y, q);
            q  = fmaf(v.z, v.z, q);  q  = fmaf(v.w, v.w, q);
            c0 = fmaf(b0.x, v.x, c0); c0 = fmaf(b0.y, v.y, c0);
            c0 = fmaf(b0.z, v.z, c0); c0 = fmaf(b0.w, v.w, c0);
            c1 = fmaf(b1.x, v.x, c1); c1 = fmaf(b1.y, v.y, c1);
            c1 = fmaf(b1.z, v.z, c1); c1 = fmaf(b1.w, v.w, c1);
            c2 = fmaf(b2.x, v.x, c2); c2 = fmaf(b2.y, v.y, c2);
            c2 = fmaf(b2.z, v.z, c2); c2 = fmaf(b2.w, v.w, c2);
            c3 = fmaf(b3.x, v.x, c3); c3 = fmaf(b3.y, v.y, c3);
            c3 = fmaf(b3.z, v.z, c3); c3 = fmaf(b3.w, v.w, c3);
        }
        // reduce within 8-lane groups: 3 butterfly steps, 4 j's at once
        #pragma unroll
        for (int o = 1; o < 8; o <<= 1) {
            q  += __shfl_xor_sync(0xffffffffu, q,  o);
            c0 += __shfl_xor_sync(0xffffffffu, c0, o);
            c1 += __shfl_xor_sync(0xffffffffu, c1, o);
            c2 += __shfl_xor_sync(0xffffffffu, c2, o);
            c3 += __shfl_xor_sync(0xffffffffu, c3, o);
        }
        if (kk == 0) {
            sssq[j]    = q;
            Drow[0][j] = c0;
            Drow[1][j] = c1;
            Drow[2][j] = c2;
            Drow[3][j] = c3;
        }
    }
    __syncthreads();

    // ---- Parallel epilogue: raw dot -> distance, thread t = column j ----
    {
        float sj = rsqrtf(fmaxf(sssq[t], 1e-24f));
        #pragma unroll
        for (int aa = 0; aa < ANCH; aa++) {
            float sa = rsqrtf(fmaxf(sssq[a0 + aa], 1e-24f));
            float d2 = 2.0f - 2.0f * Drow[aa][t] * sa * sj;
            d2 = fmaxf(d2, 0.0f);
            Drow[aa][t] = (d2 > 0.0f) ? sqrtf(d2) : 0.0f;
        }
    }
    __syncthreads();

    // ---- Phase 3+4: per anchor, ballot-compaction of positives + negative scan ----
    float lsum = 0.0f;
    int   lcnt = 0;
    for (int aa = 0; aa < ANCH; aa++) {
        const int a  = a0 + aa;
        const int la = slab[a];
        bool isp = (slab[t] == la) && (t != a);
        unsigned m = __ballot_sync(0xffffffffu, isp);
        if (lane == 0) wcnt[w] = __popc(m);
        __syncthreads();
        int off = 0, npos = 0;
        #pragma unroll
        for (int i = 0; i < NWARP; i++) {
            if (i < w) off += wcnt[i];
            npos += wcnt[i];
        }
        if (isp) pd[off + __popc(m & ((1u << lane) - 1u))] = Drow[aa][t];
        __syncthreads();

        if (slab[t] != la) {
            float dn = Drow[aa][t];
            for (int i = 0; i < npos; i++) {
                float tm = dn - pd[i];
                // semihard & loss>0  <=>  0 < tm < MARGIN (tm==MARGIN adds 0)
                if (tm > 0.0f && tm < MARGIN) { lsum += (MARGIN - tm); lcnt++; }
            }
        }
        __syncthreads();
    }

    // ---- Block reduction (fixed order, deterministic) ----
    #pragma unroll
    for (int o = 16; o > 0; o >>= 1) {
        lsum += __shfl_xor_sync(0xffffffffu, lsum, o);
        lcnt += __shfl_xor_sync(0xffffffffu, lcnt, o);
    }
    if (lane == 0) { rsum[w] = lsum; rcnt[w] = lcnt; }
    __syncthreads();
    if (t == 0) {
        float s = 0.0f; int c = 0;
        #pragma unroll
        for (int i = 0; i < NWARP; i++) { s += rsum[i]; c += rcnt[i]; }
        g_psum[blockIdx.x] = s;
        g_pcnt[blockIdx.x] = c;
        __threadfence();
        unsigned old = atomicAdd(&g_flag, 1u);
        s_last = (old == NBLK - 1) ? 1 : 0;
    }
    __syncthreads();

    // ---- Last block folds the 96 partials (deterministic order) ----
    if (s_last) {
        float s2 = (t < NBLK) ? g_psum[t] : 0.0f;
        int   c2 = (t < NBLK) ? g_pcnt[t] : 0;
        #pragma unroll
        for (int o = 16; o > 0; o >>= 1) {
            s2 += __shfl_xor_sync(0xffffffffu, s2, o);
            c2 += __shfl_xor_sync(0xffffffffu, c2, o);
        }
        if (lane == 0 && w < 3) { rsum[w] = s2; rcnt[w] = c2; }
        __syncthreads();
        if (t == 0) {
            float ts = rsum[0] + rsum[1] + rsum[2];
            int   tc = rcnt[0] + rcnt[1] + rcnt[2];
            out[0] = (tc > 0) ? (ts / (float)tc) : 0.0f;
            g_flag = 0;   // reset for next graph replay
        }
    }
}

extern "C" void kernel_launch(void* const* d_in, const int* in_sizes, int n_in,
                              void* d_out, int out_size) {
    const float* e   = (const float*)d_in[0];
    const int*   lab = (const int*)d_in[1];
    k_fused<<<NBLK, NTHR>>>(e, lab, (float*)d_out);
}